// round 5
// baseline (speedup 1.0000x reference)
#include <cuda_runtime.h>
#include <math.h>

// Problem constants
constexpr int DIMQ   = 16;    // 2^4 amplitudes
constexpr int TSTEPS = 200;
constexpr int NROTS  = 40;    // 5 * 4 qubits * 2 layers
constexpr int DEG    = 3;
constexpr int BLK    = 224;   // 7 warps, covers T=200
constexpr int NWARP  = BLK / 32;

// Fused single-qubit gate U = Rz(hz) * Ry(hy) * Rx(hx) = [[a, b], [-conj(b), conj(a)]]
struct U2 { float ar, ai, br, bi; };

__device__ __forceinline__ U2 make_u3(float hx, float hy, float hz) {
    float sx, cx, sy, cy, sz, cz;
    __sincosf(hx, &sx, &cx);
    __sincosf(hy, &sy, &cy);
    __sincosf(hz, &sz, &cz);
    float cycx = cy * cx, sysx = sy * sx, sycx = sy * cx, cysx = cy * sx;
    U2 u;
    u.ar = cz * cycx + sz * sysx;
    u.ai = cz * sysx - sz * cycx;
    u.br = -(cz * sycx + sz * cysx);
    u.bi = sz * sycx - cz * cysx;
    return u;
}

// Apply generic SU(2) gate on wire with bit mask BIT (wire w -> bit (1<<(3-w)))
template <int BIT>
__device__ __forceinline__ void apply_u(float* sr, float* si, U2 u) {
#pragma unroll
    for (int m = 0; m < DIMQ; ++m) {
        if (!(m & BIT)) {
            const int m1 = m | BIT;
            float x0r = sr[m],  x0i = si[m];
            float x1r = sr[m1], x1i = si[m1];
            sr[m]  =  u.ar * x0r - u.ai * x0i + u.br * x1r - u.bi * x1i;
            si[m]  =  u.ar * x0i + u.ai * x0r + u.br * x1i + u.bi * x1r;
            sr[m1] = -u.br * x0r - u.bi * x0i + u.ar * x1r + u.ai * x1i;
            si[m1] =  u.bi * x0r - u.br * x0i + u.ar * x1i - u.ai * x1r;
        }
    }
}

// Controlled-RX: control bit CB must be 1, acts on target pair (m, m|TB)
template <int CB, int TB>
__device__ __forceinline__ void apply_crx(float* sr, float* si, float h) {
    float s, c;
    __sincosf(h, &s, &c);
#pragma unroll
    for (int m = 0; m < DIMQ; ++m) {
        if ((m & CB) && !(m & TB)) {
            const int m1 = m | TB;
            float a0r = sr[m],  a0i = si[m];
            float a1r = sr[m1], a1i = si[m1];
            sr[m]  = c * a0r + s * a1i;
            si[m]  = c * a0i - s * a1r;
            sr[m1] = c * a1r + s * a0i;
            si[m1] = c * a1i - s * a0r;
        }
    }
}

// One ansatz layer: 20 half-angles hp[0..19]
// wires: 0->bit8, 1->bit4, 2->bit2, 3->bit1
__device__ __forceinline__ void ansatz_layer(float* sr, float* si, const float* hp) {
    apply_u<8>(sr, si, make_u3(hp[0], hp[1], hp[2]));
    apply_u<4>(sr, si, make_u3(hp[3], hp[4], hp[5]));
    apply_u<2>(sr, si, make_u3(hp[6], hp[7], hp[8]));
    apply_u<1>(sr, si, make_u3(hp[9], hp[10], hp[11]));
    // forward ring: CRX(cw=i, tw=(i+1)%4)
    apply_crx<8, 4>(sr, si, hp[12]);
    apply_crx<4, 2>(sr, si, hp[13]);
    apply_crx<2, 1>(sr, si, hp[14]);
    apply_crx<1, 8>(sr, si, hp[15]);
    // backward ring: i = 3,2,1,0 -> CRX(cw=i, tw=(i-1)%4)
    apply_crx<1, 2>(sr, si, hp[16]);
    apply_crx<2, 4>(sr, si, hp[17]);
    apply_crx<4, 8>(sr, si, hp[18]);
    apply_crx<8, 1>(sr, si, hp[19]);
}

__global__ __launch_bounds__(BLK)
void qcore_kernel(const float* __restrict__ tp,    // (B, T, 40)
                  const float* __restrict__ pc,    // (4,)
                  const float* __restrict__ mre,   // (T,)
                  const float* __restrict__ mim,   // (T,)
                  const float* __restrict__ qff,   // (20,)
                  float* __restrict__ out)         // (B, 12)
{
    const int b    = blockIdx.x;
    const int tid  = threadIdx.x;
    const int lane = tid & 31;
    const int wid  = tid >> 5;

    __shared__ float red[NWARP][32];
    __shared__ float st_s[32];   // current work state: [re0..15, im0..15]
    __shared__ float acc_s[32];  // QSVT accumulator

    float pcl[4];
#pragma unroll
    for (int i = 0; i < 4; ++i) pcl[i] = pc[i];

    if (tid < 32) {
        float v = (tid == 0) ? 1.0f : 0.0f;     // base = |0>
        st_s[tid]  = v;
        acc_s[tid] = pcl[0] * v;                // acc = c0 * base
    }

    const bool active = (tid < TSTEPS);
    float cr = 0.0f, ci = 0.0f;
    float hp[NROTS];
    if (active) {
        cr = mre[tid];
        ci = mim[tid];
        const float4* p4 =
            (const float4*)(tp + ((size_t)b * TSTEPS + tid) * NROTS);
#pragma unroll
        for (int i = 0; i < NROTS / 4; ++i) {
            float4 v = p4[i];
            hp[4 * i + 0] = 0.5f * v.x;
            hp[4 * i + 1] = 0.5f * v.y;
            hp[4 * i + 2] = 0.5f * v.z;
            hp[4 * i + 3] = 0.5f * v.w;
        }
    }
    __syncthreads();

    for (int k = 1; k <= DEG; ++k) {
        float sr[DIMQ], si[DIMQ];
#pragma unroll
        for (int j = 0; j < DIMQ; ++j) { sr[j] = st_s[j]; si[j] = st_s[16 + j]; }

        if (active) {
            ansatz_layer(sr, si, hp);
            ansatz_layer(sr, si, hp + 20);
            // weight by complex coeff (same for all b): contrib = (cr + i ci) * ev
#pragma unroll
            for (int j = 0; j < DIMQ; ++j) {
                float tr = cr * sr[j] - ci * si[j];
                float ti = cr * si[j] + ci * sr[j];
                sr[j] = tr; si[j] = ti;
            }
        } else {
#pragma unroll
            for (int j = 0; j < DIMQ; ++j) { sr[j] = 0.0f; si[j] = 0.0f; }
        }

        // warp butterfly reduction over t within each warp
#pragma unroll
        for (int j = 0; j < DIMQ; ++j) {
#pragma unroll
            for (int o = 16; o > 0; o >>= 1) {
                sr[j] += __shfl_xor_sync(0xffffffffu, sr[j], o);
                si[j] += __shfl_xor_sync(0xffffffffu, si[j], o);
            }
        }
        if (lane == 0) {
#pragma unroll
            for (int j = 0; j < DIMQ; ++j) {
                red[wid][j]      = sr[j];
                red[wid][16 + j] = si[j];
            }
        }
        __syncthreads();
        if (tid < 32) {
            float s = 0.0f;
#pragma unroll
            for (int w = 0; w < NWARP; ++w) s += red[w][tid];
            st_s[tid] = s;                  // next work state
            acc_s[tid] += pcl[k] * s;       // acc += c_k * work
        }
        __syncthreads();
    }

    // ---- final stage: normalize, qff ansatz, expectation values (thread 0) ----
    if (tid == 0) {
        float l1 = fabsf(pcl[0]) + fabsf(pcl[1]) + fabsf(pcl[2]) + fabsf(pcl[3]);
        float inv_l1 = 1.0f / l1;
        float ar[DIMQ], ai[DIMQ];
        float ss = 0.0f;
#pragma unroll
        for (int j = 0; j < DIMQ; ++j) {
            ar[j] = acc_s[j] * inv_l1;
            ai[j] = acc_s[16 + j] * inv_l1;
            ss += ar[j] * ar[j] + ai[j] * ai[j];
        }
        float inv_n = 1.0f / (sqrtf(ss) + 1e-9f);
#pragma unroll
        for (int j = 0; j < DIMQ; ++j) { ar[j] *= inv_n; ai[j] *= inv_n; }

        float qh[20];
#pragma unroll
        for (int i = 0; i < 20; ++i) qh[i] = 0.5f * qff[i];
        ansatz_layer(ar, ai, qh);

        // expectation values: out layout [X0..X3, Y0..Y3, Z0..Z3]
#pragma unroll
        for (int w = 0; w < 4; ++w) {
            const int bit = 8 >> w;
            float x = 0.0f, y = 0.0f, z = 0.0f;
#pragma unroll
            for (int m = 0; m < DIMQ; ++m) {
                if (!(m & bit)) {
                    const int m1 = m | bit;
                    // conj(s0)*s1 = (s0r*s1r + s0i*s1i) + i(s0r*s1i - s0i*s1r)
                    float zr = ar[m] * ar[m1] + ai[m] * ai[m1];
                    float zi = ar[m] * ai[m1] - ai[m] * ar[m1];
                    x += 2.0f * zr;
                    y += 2.0f * zi;
                    z += ar[m] * ar[m] + ai[m] * ai[m]
                       - ar[m1] * ar[m1] - ai[m1] * ai[m1];
                }
            }
            out[b * 12 + w]     = x;
            out[b * 12 + 4 + w] = y;
            out[b * 12 + 8 + w] = z;
        }
    }
}

extern "C" void kernel_launch(void* const* d_in, const int* in_sizes, int n_in,
                              void* d_out, int out_size) {
    const float* tp  = (const float*)d_in[0];  // timestep_params (B,T,40)
    const float* pc  = (const float*)d_in[1];  // poly_coeffs (4,)
    const float* mre = (const float*)d_in[2];  // mix_re (T,)
    const float* mim = (const float*)d_in[3];  // mix_im (T,)
    const float* qff = (const float*)d_in[4];  // qff_params (20,)
    float* out = (float*)d_out;

    const int B = in_sizes[0] / (TSTEPS * NROTS);  // 2048
    qcore_kernel<<<B, BLK>>>(tp, pc, mre, mim, qff, out);
}

// round 6
// speedup vs baseline: 1.1774x; 1.1774x over previous
#include <cuda_runtime.h>
#include <math.h>

// Problem constants
constexpr int DIMQ   = 16;
constexpr int TSTEPS = 200;
constexpr int NROTS  = 40;
constexpr int DEG    = 3;
constexpr int BLK    = 224;   // 7 warps
constexpr int NWARP  = BLK / 32;

typedef unsigned long long ull;

// ---------- packed f32x2 helpers ----------
__device__ __forceinline__ ull pack2(float lo, float hi) {
    ull r;
    asm("mov.b64 %0, {%1, %2};" : "=l"(r) : "r"(__float_as_uint(lo)), "r"(__float_as_uint(hi)));
    return r;
}
__device__ __forceinline__ ull bc2(float x) { return pack2(x, x); }
__device__ __forceinline__ void unpack2(ull v, float& lo, float& hi) {
    unsigned a, b;
    asm("mov.b64 {%0, %1}, %2;" : "=r"(a), "=r"(b) : "l"(v));
    lo = __uint_as_float(a); hi = __uint_as_float(b);
}
__device__ __forceinline__ ull swap2(ull v) {
    ull r;
    asm("{\n\t.reg .b32 lo, hi;\n\tmov.b64 {lo, hi}, %1;\n\tmov.b64 %0, {hi, lo};\n\t}"
        : "=l"(r) : "l"(v));
    return r;
}
__device__ __forceinline__ ull fma2(ull a, ull b, ull c) {
    ull d; asm("fma.rn.f32x2 %0, %1, %2, %3;" : "=l"(d) : "l"(a), "l"(b), "l"(c)); return d;
}
__device__ __forceinline__ ull mul2(ull a, ull b) {
    ull d; asm("mul.rn.f32x2 %0, %1, %2;" : "=l"(d) : "l"(a), "l"(b)); return d;
}
__device__ __forceinline__ ull add2(ull a, ull b) {
    ull d; asm("add.rn.f32x2 %0, %1, %2;" : "=l"(d) : "l"(a), "l"(b)); return d;
}

// ---------- fused single-qubit gate coefficients ----------
struct U2 { float ar, ai, br, bi; };

__device__ __forceinline__ U2 make_u3(float hx, float hy, float hz) {
    float sx, cx, sy, cy, sz, cz;
    __sincosf(hx, &sx, &cx);
    __sincosf(hy, &sy, &cy);
    __sincosf(hz, &sz, &cz);
    float cycx = cy * cx, sysx = sy * sx, sycx = sy * cx, cysx = cy * sx;
    U2 u;
    u.ar = cz * cycx + sz * sysx;
    u.ai = cz * sysx - sz * cycx;
    u.br = -(cz * sycx + sz * cysx);
    u.bi = sz * sycx - cz * cysx;
    return u;
}

// ---------- packed gate applications ----------
// State: PR[j] = (re[2j], re[2j+1]), PI[j] = (im[2j], im[2j+1]), j=0..7

// U gate on amplitude-bit >= 2: packed-bit PB = BIT>>1, pure SIMD.
template <int PB>
__device__ __forceinline__ void u_hi(ull* PR, ull* PI, const float* g) {
    ull ar  = bc2(g[0]),  ai  = bc2(g[1]),  br  = bc2(g[2]),  bi = bc2(g[3]);
    ull nai = bc2(-g[1]), nbr = bc2(-g[2]), nbi = bc2(-g[3]);
#pragma unroll
    for (int j = 0; j < 8; ++j) if (!(j & PB)) {
        const int j1 = j | PB;
        ull x0r = PR[j], x0i = PI[j], x1r = PR[j1], x1i = PI[j1];
        PR[j]  = fma2(ar,  x0r, fma2(nai, x0i, fma2(br, x1r, mul2(nbi, x1i))));
        PI[j]  = fma2(ar,  x0i, fma2(ai,  x0r, fma2(br, x1i, mul2(bi,  x1r))));
        PR[j1] = fma2(nbr, x0r, fma2(nbi, x0i, fma2(ar, x1r, mul2(ai,  x1i))));
        PI[j1] = fma2(bi,  x0r, fma2(nbr, x0i, fma2(ar, x1i, mul2(nai, x1r))));
    }
}

// U gate on amplitude-bit 1: pair lives inside each packed register.
__device__ __forceinline__ void u_b1(ull* PR, ull* PI, const float* g) {
    float ar = g[0], ai = g[1], br = g[2], bi = g[3];
    ull arar   = bc2(ar);
    ull brnbr  = pack2(br, -br);
    ull naiai  = pack2(-ai, ai);
    ull nbinbi = bc2(-bi);
    ull ainai  = pack2(ai, -ai);
    ull bibi   = bc2(bi);
#pragma unroll
    for (int j = 0; j < 8; ++j) {
        ull SR = PR[j], SI = PI[j];
        ull sSR = swap2(SR), sSI = swap2(SI);
        PR[j] = fma2(arar, SR, fma2(brnbr, sSR, fma2(naiai, SI, mul2(nbinbi, sSI))));
        PI[j] = fma2(arar, SI, fma2(brnbr, sSI, fma2(ainai, SR, mul2(bibi,  sSR))));
    }
}

// CRX with control bit >=2 and target bit >=2 (packed bits PCB, PTB)
template <int PCB, int PTB>
__device__ __forceinline__ void crx_hh(ull* PR, ull* PI, float c, float s) {
    ull c2 = bc2(c), s2 = bc2(s), ns2 = bc2(-s);
#pragma unroll
    for (int j = 0; j < 8; ++j) if ((j & PCB) && !(j & PTB)) {
        const int j1 = j | PTB;
        ull a0r = PR[j], a0i = PI[j], a1r = PR[j1], a1i = PI[j1];
        PR[j]  = fma2(c2, a0r, mul2(s2,  a1i));
        PI[j]  = fma2(c2, a0i, mul2(ns2, a1r));
        PR[j1] = fma2(c2, a1r, mul2(s2,  a0i));
        PI[j1] = fma2(c2, a1i, mul2(ns2, a0r));
    }
}

// CRX with control bit == 1 (bit0): only hi halves change. Target packed bit PTB.
template <int PTB>
__device__ __forceinline__ void crx_c1(ull* PR, ull* PI, float c, float s) {
    ull oc  = pack2(1.0f, c);
    ull zs  = pack2(0.0f, s);
    ull zns = pack2(0.0f, -s);
#pragma unroll
    for (int j = 0; j < 8; ++j) if (!(j & PTB)) {
        const int j1 = j | PTB;
        ull a0r = PR[j], a0i = PI[j], a1r = PR[j1], a1i = PI[j1];
        PR[j]  = fma2(oc, a0r, mul2(zs,  a1i));
        PI[j]  = fma2(oc, a0i, mul2(zns, a1r));
        PR[j1] = fma2(oc, a1r, mul2(zs,  a0i));
        PI[j1] = fma2(oc, a1i, mul2(zns, a0r));
    }
}

// CRX with target bit == 1 (bit0): pair inside packed reg; control packed bit PCB.
template <int PCB>
__device__ __forceinline__ void crx_t1(ull* PR, ull* PI, float c, float s) {
    ull c2 = bc2(c), s2 = bc2(s), ns2 = bc2(-s);
#pragma unroll
    for (int j = 0; j < 8; ++j) if (j & PCB) {
        ull SR = PR[j], SI = PI[j];
        PR[j] = fma2(c2, SR, mul2(s2,  swap2(SI)));
        PI[j] = fma2(c2, SI, mul2(ns2, swap2(SR)));
    }
}

// One ansatz layer, coefficients precomputed:
// ug: 4 gates x (ar,ai,br,bi); cs: 8 crx x (c,s)
__device__ __forceinline__ void layer_packed(ull* PR, ull* PI,
                                             const float* ug, const float* cs) {
    u_hi<4>(PR, PI, ug + 0);    // wire0, BIT8
    u_hi<2>(PR, PI, ug + 4);    // wire1, BIT4
    u_hi<1>(PR, PI, ug + 8);    // wire2, BIT2
    u_b1   (PR, PI, ug + 12);   // wire3, BIT1
    crx_hh<4, 2>(PR, PI, cs[0],  cs[1]);   // crx<8,4>
    crx_hh<2, 1>(PR, PI, cs[2],  cs[3]);   // crx<4,2>
    crx_t1<1>   (PR, PI, cs[4],  cs[5]);   // crx<2,1>
    crx_c1<4>   (PR, PI, cs[6],  cs[7]);   // crx<1,8>
    crx_c1<1>   (PR, PI, cs[8],  cs[9]);   // crx<1,2>
    crx_hh<1, 2>(PR, PI, cs[10], cs[11]);  // crx<2,4>
    crx_hh<2, 4>(PR, PI, cs[12], cs[13]);  // crx<4,8>
    crx_t1<4>   (PR, PI, cs[14], cs[15]);  // crx<8,1>
}

// ---------- scalar versions for the tiny final stage ----------
template <int BIT>
__device__ __forceinline__ void apply_u_sc(float* sr, float* si, U2 u) {
#pragma unroll
    for (int m = 0; m < DIMQ; ++m) if (!(m & BIT)) {
        const int m1 = m | BIT;
        float x0r = sr[m], x0i = si[m], x1r = sr[m1], x1i = si[m1];
        sr[m]  =  u.ar * x0r - u.ai * x0i + u.br * x1r - u.bi * x1i;
        si[m]  =  u.ar * x0i + u.ai * x0r + u.br * x1i + u.bi * x1r;
        sr[m1] = -u.br * x0r - u.bi * x0i + u.ar * x1r + u.ai * x1i;
        si[m1] =  u.bi * x0r - u.br * x0i + u.ar * x1i - u.ai * x1r;
    }
}
template <int CB, int TB>
__device__ __forceinline__ void apply_crx_sc(float* sr, float* si, float h) {
    float s, c;
    __sincosf(h, &s, &c);
#pragma unroll
    for (int m = 0; m < DIMQ; ++m) if ((m & CB) && !(m & TB)) {
        const int m1 = m | TB;
        float a0r = sr[m], a0i = si[m], a1r = sr[m1], a1i = si[m1];
        sr[m]  = c * a0r + s * a1i;
        si[m]  = c * a0i - s * a1r;
        sr[m1] = c * a1r + s * a0i;
        si[m1] = c * a1i - s * a0r;
    }
}
__device__ __forceinline__ void ansatz_layer_sc(float* sr, float* si, const float* hp) {
    apply_u_sc<8>(sr, si, make_u3(hp[0], hp[1], hp[2]));
    apply_u_sc<4>(sr, si, make_u3(hp[3], hp[4], hp[5]));
    apply_u_sc<2>(sr, si, make_u3(hp[6], hp[7], hp[8]));
    apply_u_sc<1>(sr, si, make_u3(hp[9], hp[10], hp[11]));
    apply_crx_sc<8, 4>(sr, si, hp[12]);
    apply_crx_sc<4, 2>(sr, si, hp[13]);
    apply_crx_sc<2, 1>(sr, si, hp[14]);
    apply_crx_sc<1, 8>(sr, si, hp[15]);
    apply_crx_sc<1, 2>(sr, si, hp[16]);
    apply_crx_sc<2, 4>(sr, si, hp[17]);
    apply_crx_sc<4, 8>(sr, si, hp[18]);
    apply_crx_sc<8, 1>(sr, si, hp[19]);
}

__global__ __launch_bounds__(BLK, 2)
void qcore_kernel(const float* __restrict__ tp,    // (B, T, 40)
                  const float* __restrict__ pc,    // (4,)
                  const float* __restrict__ mre,   // (T,)
                  const float* __restrict__ mim,   // (T,)
                  const float* __restrict__ qff,   // (20,)
                  float* __restrict__ out)         // (B, 12)
{
    const int b    = blockIdx.x;
    const int tid  = threadIdx.x;
    const int lane = tid & 31;
    const int wid  = tid >> 5;

    __shared__ float red[NWARP][32];
    __shared__ float st_s[32];   // work state: [re0..15, im0..15]
    __shared__ float acc_s[32];  // QSVT accumulator

    float pcl[4];
#pragma unroll
    for (int i = 0; i < 4; ++i) pcl[i] = pc[i];

    if (tid < 32) {
        float v = (tid == 0) ? 1.0f : 0.0f;
        st_s[tid]  = v;
        acc_s[tid] = pcl[0] * v;
    }

    const bool active = (tid < TSTEPS);
    float cr = 0.0f, ci = 0.0f;
    // Precomputed gate coefficients (loop-invariant across k)
    float ug[2][16];   // per layer: 4 U gates x (ar,ai,br,bi)
    float cs[2][16];   // per layer: 8 CRX x (c,s)
    if (active) {
        cr = mre[tid];
        ci = mim[tid];
        float hp[NROTS];
        const float4* p4 = (const float4*)(tp + ((size_t)b * TSTEPS + tid) * NROTS);
#pragma unroll
        for (int i = 0; i < NROTS / 4; ++i) {
            float4 v = p4[i];
            hp[4 * i + 0] = 0.5f * v.x;
            hp[4 * i + 1] = 0.5f * v.y;
            hp[4 * i + 2] = 0.5f * v.z;
            hp[4 * i + 3] = 0.5f * v.w;
        }
#pragma unroll
        for (int L = 0; L < 2; ++L) {
            const int base = 20 * L;
#pragma unroll
            for (int q = 0; q < 4; ++q) {
                U2 u = make_u3(hp[base + 3 * q], hp[base + 3 * q + 1], hp[base + 3 * q + 2]);
                ug[L][4 * q + 0] = u.ar;
                ug[L][4 * q + 1] = u.ai;
                ug[L][4 * q + 2] = u.br;
                ug[L][4 * q + 3] = u.bi;
            }
#pragma unroll
            for (int r = 0; r < 8; ++r) {
                float s, c;
                __sincosf(hp[base + 12 + r], &s, &c);
                cs[L][2 * r + 0] = c;
                cs[L][2 * r + 1] = s;
            }
        }
    }
    __syncthreads();

    const unsigned FULL = 0xffffffffu;

    for (int k = 1; k <= DEG; ++k) {
        ull PR[8], PI[8];
#pragma unroll
        for (int j = 0; j < 8; ++j) {
            PR[j] = pack2(st_s[2 * j],      st_s[2 * j + 1]);
            PI[j] = pack2(st_s[16 + 2 * j], st_s[17 + 2 * j]);
        }

        if (active) {
            layer_packed(PR, PI, ug[0], cs[0]);
            layer_packed(PR, PI, ug[1], cs[1]);
            // weight by complex coeff (cr + i ci)
            ull crp = bc2(cr), cip = bc2(ci), ncip = bc2(-ci);
#pragma unroll
            for (int j = 0; j < 8; ++j) {
                ull r0 = PR[j], i0 = PI[j];
                PR[j] = fma2(crp, r0, mul2(ncip, i0));
                PI[j] = fma2(crp, i0, mul2(cip,  r0));
            }
        } else {
#pragma unroll
            for (int j = 0; j < 8; ++j) { PR[j] = 0ull; PI[j] = 0ull; }
        }

        // ---- register-exchange butterfly: lane L ends with component L ----
        // components: 0..15 = re, 16..31 = im
        ull W[8];
        {
            const bool up = (lane & 16);
#pragma unroll
            for (int j = 0; j < 8; ++j) {
                ull keep = up ? PI[j] : PR[j];
                ull give = up ? PR[j] : PI[j];
                W[j] = add2(keep, __shfl_xor_sync(FULL, give, 16));
            }
        }
        ull X[4];
        {
            const bool up = (lane & 8);
#pragma unroll
            for (int j = 0; j < 4; ++j) {
                ull keep = up ? W[j + 4] : W[j];
                ull give = up ? W[j] : W[j + 4];
                X[j] = add2(keep, __shfl_xor_sync(FULL, give, 8));
            }
        }
        ull Y[2];
        {
            const bool up = (lane & 4);
#pragma unroll
            for (int j = 0; j < 2; ++j) {
                ull keep = up ? X[j + 2] : X[j];
                ull give = up ? X[j] : X[j + 2];
                Y[j] = add2(keep, __shfl_xor_sync(FULL, give, 4));
            }
        }
        ull Z;
        {
            const bool up = (lane & 2);
            ull keep = up ? Y[1] : Y[0];
            ull give = up ? Y[0] : Y[1];
            Z = add2(keep, __shfl_xor_sync(FULL, give, 2));
        }
        float res;
        {
            float zlo, zhi;
            unpack2(Z, zlo, zhi);
            float keep = (lane & 1) ? zhi : zlo;
            float give = (lane & 1) ? zlo : zhi;
            res = keep + __shfl_xor_sync(FULL, give, 1);
        }

        red[wid][lane] = res;
        __syncthreads();
        if (tid < 32) {
            float s = 0.0f;
#pragma unroll
            for (int w = 0; w < NWARP; ++w) s += red[w][tid];
            st_s[tid] = s;
            acc_s[tid] += pcl[k] * s;
        }
        __syncthreads();
    }

    // ---- final stage: normalize, qff ansatz, expectation values (thread 0) ----
    if (tid == 0) {
        float l1 = fabsf(pcl[0]) + fabsf(pcl[1]) + fabsf(pcl[2]) + fabsf(pcl[3]);
        float inv_l1 = 1.0f / l1;
        float ar[DIMQ], ai[DIMQ];
        float ss = 0.0f;
#pragma unroll
        for (int j = 0; j < DIMQ; ++j) {
            ar[j] = acc_s[j] * inv_l1;
            ai[j] = acc_s[16 + j] * inv_l1;
            ss += ar[j] * ar[j] + ai[j] * ai[j];
        }
        float inv_n = 1.0f / (sqrtf(ss) + 1e-9f);
#pragma unroll
        for (int j = 0; j < DIMQ; ++j) { ar[j] *= inv_n; ai[j] *= inv_n; }

        float qh[20];
#pragma unroll
        for (int i = 0; i < 20; ++i) qh[i] = 0.5f * qff[i];
        ansatz_layer_sc(ar, ai, qh);

#pragma unroll
        for (int w = 0; w < 4; ++w) {
            const int bit = 8 >> w;
            float x = 0.0f, y = 0.0f, z = 0.0f;
#pragma unroll
            for (int m = 0; m < DIMQ; ++m) {
                if (!(m & bit)) {
                    const int m1 = m | bit;
                    float zr = ar[m] * ar[m1] + ai[m] * ai[m1];
                    float zi = ar[m] * ai[m1] - ai[m] * ar[m1];
                    x += 2.0f * zr;
                    y += 2.0f * zi;
                    z += ar[m] * ar[m] + ai[m] * ai[m]
                       - ar[m1] * ar[m1] - ai[m1] * ai[m1];
                }
            }
            out[b * 12 + w]     = x;
            out[b * 12 + 4 + w] = y;
            out[b * 12 + 8 + w] = z;
        }
    }
}

extern "C" void kernel_launch(void* const* d_in, const int* in_sizes, int n_in,
                              void* d_out, int out_size) {
    const float* tp  = (const float*)d_in[0];
    const float* pc  = (const float*)d_in[1];
    const float* mre = (const float*)d_in[2];
    const float* mim = (const float*)d_in[3];
    const float* qff = (const float*)d_in[4];
    float* out = (float*)d_out;

    const int B = in_sizes[0] / (TSTEPS * NROTS);
    qcore_kernel<<<B, BLK>>>(tp, pc, mre, mim, qff, out);
}

// round 7
// speedup vs baseline: 1.2484x; 1.0603x over previous
#include <cuda_runtime.h>
#include <math.h>

// Problem constants
constexpr int DIMQ   = 16;
constexpr int TSTEPS = 200;
constexpr int NROTS  = 40;
constexpr int DEG    = 3;
constexpr int BLK    = 224;   // 7 warps
constexpr int NWARP  = BLK / 32;

// dynamic smem layout (floats):
//   [0, 64*BLK)        per-thread gate coefficients, i-major
//   [64*BLK, +NWARP*32) warp-reduction buffer
//   then st_s[32], acc_s[32]
constexpr int COEF_FLOATS = 64 * BLK;
constexpr int SMEM_FLOATS = COEF_FLOATS + NWARP * 32 + 32 + 32;
constexpr int SMEM_BYTES  = SMEM_FLOATS * 4;

typedef unsigned long long ull;

// ---------- packed f32x2 helpers ----------
__device__ __forceinline__ ull pack2(float lo, float hi) {
    ull r;
    asm("mov.b64 %0, {%1, %2};" : "=l"(r) : "r"(__float_as_uint(lo)), "r"(__float_as_uint(hi)));
    return r;
}
__device__ __forceinline__ ull bc2(float x) { return pack2(x, x); }
__device__ __forceinline__ void unpack2(ull v, float& lo, float& hi) {
    unsigned a, b;
    asm("mov.b64 {%0, %1}, %2;" : "=r"(a), "=r"(b) : "l"(v));
    lo = __uint_as_float(a); hi = __uint_as_float(b);
}
__device__ __forceinline__ ull swap2(ull v) {
    ull r;
    asm("{\n\t.reg .b32 lo, hi;\n\tmov.b64 {lo, hi}, %1;\n\tmov.b64 %0, {hi, lo};\n\t}"
        : "=l"(r) : "l"(v));
    return r;
}
__device__ __forceinline__ ull fma2(ull a, ull b, ull c) {
    ull d; asm("fma.rn.f32x2 %0, %1, %2, %3;" : "=l"(d) : "l"(a), "l"(b), "l"(c)); return d;
}
__device__ __forceinline__ ull mul2(ull a, ull b) {
    ull d; asm("mul.rn.f32x2 %0, %1, %2;" : "=l"(d) : "l"(a), "l"(b)); return d;
}
__device__ __forceinline__ ull add2(ull a, ull b) {
    ull d; asm("add.rn.f32x2 %0, %1, %2;" : "=l"(d) : "l"(a), "l"(b)); return d;
}

// ---------- fused single-qubit gate coefficients ----------
struct U2 { float ar, ai, br, bi; };

__device__ __forceinline__ U2 make_u3(float hx, float hy, float hz) {
    float sx, cx, sy, cy, sz, cz;
    __sincosf(hx, &sx, &cx);
    __sincosf(hy, &sy, &cy);
    __sincosf(hz, &sz, &cz);
    float cycx = cy * cx, sysx = sy * sx, sycx = sy * cx, cysx = cy * sx;
    U2 u;
    u.ar = cz * cycx + sz * sysx;
    u.ai = cz * sysx - sz * cycx;
    u.br = -(cz * sycx + sz * cysx);
    u.bi = sz * sycx - cz * cysx;
    return u;
}

// ---------- packed gate applications ----------
// State: PR[j] = (re[2j], re[2j+1]), PI[j] = (im[2j], im[2j+1]), j=0..7
// Coefficients come from smem pointer g, i-major: entry i at g[i*BLK].

// U gate on amplitude-bit >= 2: packed-bit PB = BIT>>1, pure SIMD.
template <int PB>
__device__ __forceinline__ void u_hi(ull* PR, ull* PI, const float* g) {
    const float g0 = g[0 * BLK], g1 = g[1 * BLK], g2 = g[2 * BLK], g3 = g[3 * BLK];
    ull ar  = bc2(g0),  ai  = bc2(g1),  br  = bc2(g2),  bi = bc2(g3);
    ull nai = bc2(-g1), nbr = bc2(-g2), nbi = bc2(-g3);
#pragma unroll
    for (int j = 0; j < 8; ++j) if (!(j & PB)) {
        const int j1 = j | PB;
        ull x0r = PR[j], x0i = PI[j], x1r = PR[j1], x1i = PI[j1];
        PR[j]  = fma2(ar,  x0r, fma2(nai, x0i, fma2(br, x1r, mul2(nbi, x1i))));
        PI[j]  = fma2(ar,  x0i, fma2(ai,  x0r, fma2(br, x1i, mul2(bi,  x1r))));
        PR[j1] = fma2(nbr, x0r, fma2(nbi, x0i, fma2(ar, x1r, mul2(ai,  x1i))));
        PI[j1] = fma2(bi,  x0r, fma2(nbr, x0i, fma2(ar, x1i, mul2(nai, x1r))));
    }
}

// U gate on amplitude-bit 1: pair lives inside each packed register.
__device__ __forceinline__ void u_b1(ull* PR, ull* PI, const float* g) {
    const float ar = g[0 * BLK], ai = g[1 * BLK], br = g[2 * BLK], bi = g[3 * BLK];
    ull arar   = bc2(ar);
    ull brnbr  = pack2(br, -br);
    ull naiai  = pack2(-ai, ai);
    ull nbinbi = bc2(-bi);
    ull ainai  = pack2(ai, -ai);
    ull bibi   = bc2(bi);
#pragma unroll
    for (int j = 0; j < 8; ++j) {
        ull SR = PR[j], SI = PI[j];
        ull sSR = swap2(SR), sSI = swap2(SI);
        PR[j] = fma2(arar, SR, fma2(brnbr, sSR, fma2(naiai, SI, mul2(nbinbi, sSI))));
        PI[j] = fma2(arar, SI, fma2(brnbr, sSI, fma2(ainai, SR, mul2(bibi,  sSR))));
    }
}

// CRX with control bit >=2 and target bit >=2 (packed bits PCB, PTB)
template <int PCB, int PTB>
__device__ __forceinline__ void crx_hh(ull* PR, ull* PI, const float* g) {
    const float c = g[0], s = g[BLK];
    ull c2 = bc2(c), s2 = bc2(s), ns2 = bc2(-s);
#pragma unroll
    for (int j = 0; j < 8; ++j) if ((j & PCB) && !(j & PTB)) {
        const int j1 = j | PTB;
        ull a0r = PR[j], a0i = PI[j], a1r = PR[j1], a1i = PI[j1];
        PR[j]  = fma2(c2, a0r, mul2(s2,  a1i));
        PI[j]  = fma2(c2, a0i, mul2(ns2, a1r));
        PR[j1] = fma2(c2, a1r, mul2(s2,  a0i));
        PI[j1] = fma2(c2, a1i, mul2(ns2, a0r));
    }
}

// CRX with control bit == 1 (bit0): only hi halves change. Target packed bit PTB.
template <int PTB>
__device__ __forceinline__ void crx_c1(ull* PR, ull* PI, const float* g) {
    const float c = g[0], s = g[BLK];
    ull oc  = pack2(1.0f, c);
    ull zs  = pack2(0.0f, s);
    ull zns = pack2(0.0f, -s);
#pragma unroll
    for (int j = 0; j < 8; ++j) if (!(j & PTB)) {
        const int j1 = j | PTB;
        ull a0r = PR[j], a0i = PI[j], a1r = PR[j1], a1i = PI[j1];
        PR[j]  = fma2(oc, a0r, mul2(zs,  a1i));
        PI[j]  = fma2(oc, a0i, mul2(zns, a1r));
        PR[j1] = fma2(oc, a1r, mul2(zs,  a0i));
        PI[j1] = fma2(oc, a1i, mul2(zns, a0r));
    }
}

// CRX with target bit == 1 (bit0): pair inside packed reg; control packed bit PCB.
template <int PCB>
__device__ __forceinline__ void crx_t1(ull* PR, ull* PI, const float* g) {
    const float c = g[0], s = g[BLK];
    ull c2 = bc2(c), s2 = bc2(s), ns2 = bc2(-s);
#pragma unroll
    for (int j = 0; j < 8; ++j) if (j & PCB) {
        ull SR = PR[j], SI = PI[j];
        PR[j] = fma2(c2, SR, mul2(s2,  swap2(SI)));
        PI[j] = fma2(c2, SI, mul2(ns2, swap2(SR)));
    }
}

// One ansatz layer; p = smem coefficient base for this layer, already offset by tid.
// Layout per layer (i-major, entries * BLK): 0..15 = 4 U gates x (ar,ai,br,bi),
// 16..31 = 8 CRX x (c,s).
__device__ __forceinline__ void layer_packed(ull* PR, ull* PI, const float* p) {
    u_hi<4>(PR, PI, p + 0 * BLK);    // wire0, BIT8
    u_hi<2>(PR, PI, p + 4 * BLK);    // wire1, BIT4
    u_hi<1>(PR, PI, p + 8 * BLK);    // wire2, BIT2
    u_b1   (PR, PI, p + 12 * BLK);   // wire3, BIT1
    crx_hh<4, 2>(PR, PI, p + 16 * BLK);   // crx<8,4>
    crx_hh<2, 1>(PR, PI, p + 18 * BLK);   // crx<4,2>
    crx_t1<1>   (PR, PI, p + 20 * BLK);   // crx<2,1>
    crx_c1<4>   (PR, PI, p + 22 * BLK);   // crx<1,8>
    crx_c1<1>   (PR, PI, p + 24 * BLK);   // crx<1,2>
    crx_hh<1, 2>(PR, PI, p + 26 * BLK);   // crx<2,4>
    crx_hh<2, 4>(PR, PI, p + 28 * BLK);   // crx<4,8>
    crx_t1<4>   (PR, PI, p + 30 * BLK);   // crx<8,1>
}

// ---------- scalar versions for the tiny final stage ----------
template <int BIT>
__device__ __forceinline__ void apply_u_sc(float* sr, float* si, U2 u) {
#pragma unroll
    for (int m = 0; m < DIMQ; ++m) if (!(m & BIT)) {
        const int m1 = m | BIT;
        float x0r = sr[m], x0i = si[m], x1r = sr[m1], x1i = si[m1];
        sr[m]  =  u.ar * x0r - u.ai * x0i + u.br * x1r - u.bi * x1i;
        si[m]  =  u.ar * x0i + u.ai * x0r + u.br * x1i + u.bi * x1r;
        sr[m1] = -u.br * x0r - u.bi * x0i + u.ar * x1r + u.ai * x1i;
        si[m1] =  u.bi * x0r - u.br * x0i + u.ar * x1i - u.ai * x1r;
    }
}
template <int CB, int TB>
__device__ __forceinline__ void apply_crx_sc(float* sr, float* si, float h) {
    float s, c;
    __sincosf(h, &s, &c);
#pragma unroll
    for (int m = 0; m < DIMQ; ++m) if ((m & CB) && !(m & TB)) {
        const int m1 = m | TB;
        float a0r = sr[m], a0i = si[m], a1r = sr[m1], a1i = si[m1];
        sr[m]  = c * a0r + s * a1i;
        si[m]  = c * a0i - s * a1r;
        sr[m1] = c * a1r + s * a0i;
        si[m1] = c * a1i - s * a0r;
    }
}
__device__ __forceinline__ void ansatz_layer_sc(float* sr, float* si, const float* hp) {
    apply_u_sc<8>(sr, si, make_u3(hp[0], hp[1], hp[2]));
    apply_u_sc<4>(sr, si, make_u3(hp[3], hp[4], hp[5]));
    apply_u_sc<2>(sr, si, make_u3(hp[6], hp[7], hp[8]));
    apply_u_sc<1>(sr, si, make_u3(hp[9], hp[10], hp[11]));
    apply_crx_sc<8, 4>(sr, si, hp[12]);
    apply_crx_sc<4, 2>(sr, si, hp[13]);
    apply_crx_sc<2, 1>(sr, si, hp[14]);
    apply_crx_sc<1, 8>(sr, si, hp[15]);
    apply_crx_sc<1, 2>(sr, si, hp[16]);
    apply_crx_sc<2, 4>(sr, si, hp[17]);
    apply_crx_sc<4, 8>(sr, si, hp[18]);
    apply_crx_sc<8, 1>(sr, si, hp[19]);
}

__global__ __launch_bounds__(BLK, 3)
void qcore_kernel(const float* __restrict__ tp,    // (B, T, 40)
                  const float* __restrict__ pc,    // (4,)
                  const float* __restrict__ mre,   // (T,)
                  const float* __restrict__ mim,   // (T,)
                  const float* __restrict__ qff,   // (20,)
                  float* __restrict__ out)         // (B, 12)
{
    extern __shared__ float smem[];
    float* coef  = smem;                       // 64*BLK
    float* red   = smem + COEF_FLOATS;         // NWARP*32
    float* st_s  = red + NWARP * 32;           // 32
    float* acc_s = st_s + 32;                  // 32

    const int b    = blockIdx.x;
    const int tid  = threadIdx.x;
    const int lane = tid & 31;
    const int wid  = tid >> 5;

    float pcl[4];
#pragma unroll
    for (int i = 0; i < 4; ++i) pcl[i] = pc[i];

    if (tid < 32) {
        float v = (tid == 0) ? 1.0f : 0.0f;
        st_s[tid]  = v;
        acc_s[tid] = pcl[0] * v;
    }

    const bool active = (tid < TSTEPS);
    float cr = 0.0f, ci = 0.0f;
    if (active) {
        cr = mre[tid];
        ci = mim[tid];
        float hp[NROTS];
        const float4* p4 = (const float4*)(tp + ((size_t)b * TSTEPS + tid) * NROTS);
#pragma unroll
        for (int i = 0; i < NROTS / 4; ++i) {
            float4 v = p4[i];
            hp[4 * i + 0] = 0.5f * v.x;
            hp[4 * i + 1] = 0.5f * v.y;
            hp[4 * i + 2] = 0.5f * v.z;
            hp[4 * i + 3] = 0.5f * v.w;
        }
        // precompute gate coefficients into smem (i-major, conflict-free)
        float* w = coef + tid;
#pragma unroll
        for (int L = 0; L < 2; ++L) {
            const int base = 20 * L;
            const int cbase = 32 * L;
#pragma unroll
            for (int q = 0; q < 4; ++q) {
                U2 u = make_u3(hp[base + 3 * q], hp[base + 3 * q + 1], hp[base + 3 * q + 2]);
                w[(cbase + 4 * q + 0) * BLK] = u.ar;
                w[(cbase + 4 * q + 1) * BLK] = u.ai;
                w[(cbase + 4 * q + 2) * BLK] = u.br;
                w[(cbase + 4 * q + 3) * BLK] = u.bi;
            }
#pragma unroll
            for (int r = 0; r < 8; ++r) {
                float s, c;
                __sincosf(hp[base + 12 + r], &s, &c);
                w[(cbase + 16 + 2 * r + 0) * BLK] = c;
                w[(cbase + 16 + 2 * r + 1) * BLK] = s;
            }
        }
    }
    __syncthreads();

    const unsigned FULL = 0xffffffffu;
    const float* cp0 = coef + tid;
    const float* cp1 = coef + 32 * BLK + tid;

    for (int k = 1; k <= DEG; ++k) {
        ull PR[8], PI[8];
#pragma unroll
        for (int j = 0; j < 8; ++j) {
            PR[j] = pack2(st_s[2 * j],      st_s[2 * j + 1]);
            PI[j] = pack2(st_s[16 + 2 * j], st_s[17 + 2 * j]);
        }

        if (active) {
            layer_packed(PR, PI, cp0);
            layer_packed(PR, PI, cp1);
            // weight by complex coeff (cr + i ci)
            ull crp = bc2(cr), cip = bc2(ci), ncip = bc2(-ci);
#pragma unroll
            for (int j = 0; j < 8; ++j) {
                ull r0 = PR[j], i0 = PI[j];
                PR[j] = fma2(crp, r0, mul2(ncip, i0));
                PI[j] = fma2(crp, i0, mul2(cip,  r0));
            }
        } else {
#pragma unroll
            for (int j = 0; j < 8; ++j) { PR[j] = 0ull; PI[j] = 0ull; }
        }

        // ---- register-exchange butterfly: lane L ends with component L ----
        ull W[8];
        {
            const bool up = (lane & 16);
#pragma unroll
            for (int j = 0; j < 8; ++j) {
                ull keep = up ? PI[j] : PR[j];
                ull give = up ? PR[j] : PI[j];
                W[j] = add2(keep, __shfl_xor_sync(FULL, give, 16));
            }
        }
        ull X[4];
        {
            const bool up = (lane & 8);
#pragma unroll
            for (int j = 0; j < 4; ++j) {
                ull keep = up ? W[j + 4] : W[j];
                ull give = up ? W[j] : W[j + 4];
                X[j] = add2(keep, __shfl_xor_sync(FULL, give, 8));
            }
        }
        ull Y[2];
        {
            const bool up = (lane & 4);
#pragma unroll
            for (int j = 0; j < 2; ++j) {
                ull keep = up ? X[j + 2] : X[j];
                ull give = up ? X[j] : X[j + 2];
                Y[j] = add2(keep, __shfl_xor_sync(FULL, give, 4));
            }
        }
        ull Z;
        {
            const bool up = (lane & 2);
            ull keep = up ? Y[1] : Y[0];
            ull give = up ? Y[0] : Y[1];
            Z = add2(keep, __shfl_xor_sync(FULL, give, 2));
        }
        float res;
        {
            float zlo, zhi;
            unpack2(Z, zlo, zhi);
            float keep = (lane & 1) ? zhi : zlo;
            float give = (lane & 1) ? zlo : zhi;
            res = keep + __shfl_xor_sync(FULL, give, 1);
        }

        red[wid * 32 + lane] = res;
        __syncthreads();
        if (tid < 32) {
            float s = 0.0f;
#pragma unroll
            for (int w = 0; w < NWARP; ++w) s += red[w * 32 + tid];
            st_s[tid] = s;
            acc_s[tid] += pcl[k] * s;
        }
        __syncthreads();
    }

    // ---- final stage: normalize, qff ansatz, expectation values (thread 0) ----
    if (tid == 0) {
        float l1 = fabsf(pcl[0]) + fabsf(pcl[1]) + fabsf(pcl[2]) + fabsf(pcl[3]);
        float inv_l1 = 1.0f / l1;
        float ar[DIMQ], ai[DIMQ];
        float ss = 0.0f;
#pragma unroll
        for (int j = 0; j < DIMQ; ++j) {
            ar[j] = acc_s[j] * inv_l1;
            ai[j] = acc_s[16 + j] * inv_l1;
            ss += ar[j] * ar[j] + ai[j] * ai[j];
        }
        float inv_n = 1.0f / (sqrtf(ss) + 1e-9f);
#pragma unroll
        for (int j = 0; j < DIMQ; ++j) { ar[j] *= inv_n; ai[j] *= inv_n; }

        float qh[20];
#pragma unroll
        for (int i = 0; i < 20; ++i) qh[i] = 0.5f * qff[i];
        ansatz_layer_sc(ar, ai, qh);

#pragma unroll
        for (int w = 0; w < 4; ++w) {
            const int bit = 8 >> w;
            float x = 0.0f, y = 0.0f, z = 0.0f;
#pragma unroll
            for (int m = 0; m < DIMQ; ++m) {
                if (!(m & bit)) {
                    const int m1 = m | bit;
                    float zr = ar[m] * ar[m1] + ai[m] * ai[m1];
                    float zi = ar[m] * ai[m1] - ai[m] * ar[m1];
                    x += 2.0f * zr;
                    y += 2.0f * zi;
                    z += ar[m] * ar[m] + ai[m] * ai[m]
                       - ar[m1] * ar[m1] - ai[m1] * ai[m1];
                }
            }
            out[b * 12 + w]     = x;
            out[b * 12 + 4 + w] = y;
            out[b * 12 + 8 + w] = z;
        }
    }
}

extern "C" void kernel_launch(void* const* d_in, const int* in_sizes, int n_in,
                              void* d_out, int out_size) {
    const float* tp  = (const float*)d_in[0];
    const float* pc  = (const float*)d_in[1];
    const float* mre = (const float*)d_in[2];
    const float* mim = (const float*)d_in[3];
    const float* qff = (const float*)d_in[4];
    float* out = (float*)d_out;

    cudaFuncSetAttribute(qcore_kernel,
                         cudaFuncAttributeMaxDynamicSharedMemorySize, SMEM_BYTES);

    const int B = in_sizes[0] / (TSTEPS * NROTS);
    qcore_kernel<<<B, BLK, SMEM_BYTES>>>(tp, pc, mre, mim, qff, out);
}